// round 6
// baseline (speedup 1.0000x reference)
#include <cuda_runtime.h>
#include <math.h>
#include <cfloat>

#ifndef M_PI
#define M_PI 3.14159265358979323846
#endif

#define NPIX 10000      // 100*100
#define SIDE 100
#define SS   200
#define KH   101        // rfft half-width
#define RR   360
#define NB   2
#define NIMG (NB*RR)    // 720
#define SPEC (SS*KH)    // 20200
#define EPSF 1e-12f

// ---------------- static device scratch (no allocations allowed) ----------------
__device__ float  d_h1[4*9*NPIX];          // conv1 outputs (rec b0,b1, lig b0,b1)
__device__ float  d_feat[4*2*NPIX];        // features
__device__ float  d_rot[NIMG*2*NPIX];      // rotated ligand features
__device__ float2 d_rf[4*SPEC];            // receptor spectra [b][ch]
__device__ float2 d_G[4*SPEC];             // combine coefs [b][ch]
__device__ float2 d_SF[NIMG*SPEC];         // combined spectrum per (b,r)
__device__ float2 d_Binv[NIMG*SPEC];       // inverse stage-1 result
__device__ float  d_blockmax[NIMG];
__device__ float  d_pos[NB];
__device__ float2 d_wf[SS];                // e^{-2pi i t/200}
__device__ float2 d_wi[SS];                // e^{+2pi i t/200}
__device__ float2 d_rtrig[RR];             // (cos, sin) per rotation

__device__ __forceinline__ float2 cmul(float2 a, float2 b){
    return make_float2(fmaf(a.x, b.x, -a.y*b.y), fmaf(a.x, b.y, a.y*b.x));
}

// ---------------- init: twiddle + rotation tables (recomputed every call) ----------------
__global__ void k_init(){
    int t = threadIdx.x;
    if (t < SS){
        double ang = -2.0 * M_PI * (double)t / 200.0;
        d_wf[t] = make_float2((float)cos(ang), (float)sin(ang));
        d_wi[t] = make_float2((float)cos(ang), (float)-sin(ang));
    }
    if (t < RR){
        float th = (float)(-M_PI + (double)t * (2.0 * M_PI / 360.0));
        d_rtrig[t] = make_float2((float)cos((double)th), (float)sin((double)th));
    }
}

// ---------------- conv1 + field norm (9 channels) ----------------
__global__ void k_conv1(const float* __restrict__ rec, const float* __restrict__ lig,
                        const float* __restrict__ w1){
    int idx = blockIdx.x*blockDim.x + threadIdx.x;
    if (idx >= 4*NPIX) return;
    int t = idx / NPIX, p = idx % NPIX;
    int y = p / SIDE, x = p % SIDE;
    const float* src = (t < 2) ? rec + t*NPIX : lig + (t-2)*NPIX;
    float acc[9];
#pragma unroll
    for (int o = 0; o < 9; o++) acc[o] = 0.f;
    for (int dy = 0; dy < 5; dy++){
        int yy = y + dy - 2; if (yy < 0 || yy >= SIDE) continue;
        for (int dx = 0; dx < 5; dx++){
            int xx = x + dx - 2; if (xx < 0 || xx >= SIDE) continue;
            float v = src[yy*SIDE + xx];
#pragma unroll
            for (int o = 0; o < 9; o++) acc[o] = fmaf(w1[o*25 + dy*5 + dx], v, acc[o]);
        }
    }
    float out[9];
    { float n = sqrtf(acc[0]*acc[0] + EPSF); out[0] = acc[0] * (n/(n+EPSF)); }
#pragma unroll
    for (int g = 0; g < 4; g++){
        int a = 1 + 2*g;
        float n = sqrtf(acc[a]*acc[a] + acc[a+1]*acc[a+1] + EPSF);
        float s = n/(n+EPSF);
        out[a] = acc[a]*s; out[a+1] = acc[a+1]*s;
    }
#pragma unroll
    for (int o = 0; o < 9; o++) d_h1[(t*9 + o)*NPIX + p] = out[o];
}

// ---------------- conv2 + field norm + feature construction ----------------
__global__ void k_conv2(const float* __restrict__ w2){
    int idx = blockIdx.x*blockDim.x + threadIdx.x;
    if (idx >= 4*NPIX) return;
    int t = idx / NPIX, p = idx % NPIX;
    int y = p / SIDE, x = p % SIDE;
    float h[3] = {0.f, 0.f, 0.f};
    for (int ic = 0; ic < 9; ic++){
        const float* base = d_h1 + (t*9 + ic)*NPIX;
        for (int dy = 0; dy < 5; dy++){
            int yy = y + dy - 2; if (yy < 0 || yy >= SIDE) continue;
            for (int dx = 0; dx < 5; dx++){
                int xx = x + dx - 2; if (xx < 0 || xx >= SIDE) continue;
                float v = base[yy*SIDE + xx];
#pragma unroll
                for (int oc = 0; oc < 3; oc++)
                    h[oc] = fmaf(w2[(oc*9 + ic)*25 + dy*5 + dx], v, h[oc]);
            }
        }
    }
    float n0 = sqrtf(h[0]*h[0] + EPSF);
    float o0 = h[0] * (n0/(n0+EPSF));
    float n1 = sqrtf(h[1]*h[1] + h[2]*h[2] + EPSF);
    float s  = n1/(n1+EPSF);
    float o1 = h[1]*s, o2 = h[2]*s;
    d_feat[(t*2 + 0)*NPIX + p] = fabsf(o0);
    d_feat[(t*2 + 1)*NPIX + p] = sqrtf(o1*o1 + o2*o2 + EPSF);
}

// ---------------- bilinear rotation of ligand features ----------------
__global__ void k_rot(){
    int idx = blockIdx.x*blockDim.x + threadIdx.x;
    if (idx >= NIMG*NPIX) return;
    int img = idx / NPIX, p = idx % NPIX;
    int b = img / RR, r = img % RR;
    int i = p / SIDE, j = p % SIDE;
    float2 cs = d_rtrig[r];
    float ct = cs.x, st = cs.y;
    const float c = 49.5f;
    float xs = (float)j - c, ys = (float)i - c;
    float xq =  ct*xs + st*ys + c;
    float yq = -st*xs + ct*ys + c;
    float x0f = floorf(xq), y0f = floorf(yq);
    float wx = xq - x0f, wy = yq - y0f;
    int x0 = (int)x0f, y0 = (int)y0f;
    float w00 = (1.f-wy)*(1.f-wx), w01 = (1.f-wy)*wx;
    float w10 = wy*(1.f-wx),       w11 = wy*wx;
    bool vx0 = (x0 >= 0 && x0 < SIDE), vx1 = (x0+1 >= 0 && x0+1 < SIDE);
    bool vy0 = (y0 >= 0 && y0 < SIDE), vy1 = (y0+1 >= 0 && y0+1 < SIDE);
    int cx0 = min(max(x0, 0), SIDE-1),   cx1 = min(max(x0+1, 0), SIDE-1);
    int cy0 = min(max(y0, 0), SIDE-1),   cy1 = min(max(y0+1, 0), SIDE-1);
#pragma unroll
    for (int ch = 0; ch < 2; ch++){
        const float* base = d_feat + ((2 + b)*2 + ch)*NPIX;
        float g00 = (vy0 && vx0) ? base[cy0*SIDE + cx0] : 0.f;
        float g01 = (vy0 && vx1) ? base[cy0*SIDE + cx1] : 0.f;
        float g10 = (vy1 && vx0) ? base[cy1*SIDE + cx0] : 0.f;
        float g11 = (vy1 && vx1) ? base[cy1*SIDE + cx1] : 0.f;
        d_rot[(img*2 + ch)*NPIX + p] = g00*w00 + g01*w01 + g10*w10 + g11*w11;
    }
}

// ---------------- forward DFT stage 1 (over y): T1[k1][x] = sum_y img[y][x] e^{-2pi i k1 y/200} ----------------
__device__ __forceinline__ void fwd_stage1(const float* s_img, float2* s_T1,
                                           const float2* s_w, int tid, int bd){
    for (int c = tid; c < 5000; c += bd){
        int x = c % SIDE, k1b = (c / SIDE) * 4;
        float2 w[4], st[4], acc[4];
#pragma unroll
        for (int j = 0; j < 4; j++){
            w[j] = make_float2(1.f, 0.f); st[j] = s_w[k1b + j]; acc[j] = make_float2(0.f, 0.f);
        }
        for (int y = 0; y < SIDE; y++){
            float v = s_img[y*SIDE + x];
#pragma unroll
            for (int j = 0; j < 4; j++){
                acc[j].x = fmaf(v, w[j].x, acc[j].x);
                acc[j].y = fmaf(v, w[j].y, acc[j].y);
                w[j] = cmul(w[j], st[j]);
            }
        }
#pragma unroll
        for (int j = 0; j < 4; j++) s_T1[(k1b + j)*SIDE + x] = acc[j];
    }
}

// ---------------- receptor FFT: full rfft2 spectrum per (b, ch) ----------------
__global__ void k_fft_rec(){
    extern __shared__ float sm[];
    float*  s_img = sm;
    float2* s_T1  = (float2*)(sm + NPIX);
    float2* s_w   = s_T1 + SS*SIDE;
    int tid = threadIdx.x, bd = blockDim.x;
    int q = blockIdx.x;                   // b*2 + ch
    const float* src = d_feat + q*NPIX;   // receptor images occupy feat[0..3]*NPIX
    for (int i = tid; i < NPIX; i += bd) s_img[i] = src[i];
    for (int i = tid; i < SS;   i += bd) s_w[i]   = d_wf[i];
    __syncthreads();
    fwd_stage1(s_img, s_T1, s_w, tid, bd);
    __syncthreads();
    for (int c = tid; c < SS*26; c += bd){
        int k1 = c / 26, k2b = (c % 26) * 4;
        float2 w[4], st[4], acc[4];
#pragma unroll
        for (int j = 0; j < 4; j++){
            w[j] = make_float2(1.f, 0.f); st[j] = s_w[k2b + j]; acc[j] = make_float2(0.f, 0.f);
        }
        for (int x = 0; x < SIDE; x++){
            float2 tv = s_T1[k1*SIDE + x];
#pragma unroll
            for (int j = 0; j < 4; j++){
                acc[j].x = fmaf(tv.x, w[j].x, fmaf(-tv.y, w[j].y, acc[j].x));
                acc[j].y = fmaf(tv.x, w[j].y, fmaf( tv.y, w[j].x, acc[j].y));
                w[j] = cmul(w[j], st[j]);
            }
        }
#pragma unroll
        for (int j = 0; j < 4; j++){
            int k2 = k2b + j;
            if (k2 < KH) d_rf[q*SPEC + k1*KH + k2] = acc[j];
        }
    }
}

// ---------------- combine coefficients from receptor spectra ----------------
__global__ void k_gcoef(const float* __restrict__ bW, const float* __restrict__ c1,
                        const float* __restrict__ c2, const float* __restrict__ bu){
    int idx = blockIdx.x*blockDim.x + threadIdx.x;
    if (idx >= NB*SPEC) return;
    int b = idx / SPEC, i = idx % SPEC;
    float2 rb = d_rf[(b*2 + 0)*SPEC + i];
    float2 rB = d_rf[(b*2 + 1)*SPEC + i];
    float2 crb = make_float2(rb.x, -rb.y);
    float2 crB = make_float2(rB.x, -rB.y);
    float wb = bW[0], wc1 = c1[0], wc2 = c2[0], wk = bu[0];
    d_G[(b*2 + 0)*SPEC + i] = make_float2(wb*crb.x + wc2*crB.x,  wb*crb.y + wc2*crB.y);
    d_G[(b*2 + 1)*SPEC + i] = make_float2(wc1*crb.x - wk*crB.x,  wc1*crb.y - wk*crB.y);
}

// ---------------- ligand FFT + frequency combine: SF = lb*Gb + lB*GB ----------------
__global__ void k_fft_lig(){
    extern __shared__ float sm[];
    float*  s_img = sm;
    float2* s_T1  = (float2*)(sm + NPIX);
    float2* s_w   = s_T1 + SS*SIDE;
    int tid = threadIdx.x, bd = blockDim.x;
    int img = blockIdx.x;
    int b = img / RR;
    for (int i = tid; i < SS; i += bd) s_w[i] = d_wf[i];
    for (int ch = 0; ch < 2; ch++){
        const float* src = d_rot + (img*2 + ch)*NPIX;
        for (int i = tid; i < NPIX; i += bd) s_img[i] = src[i];
        __syncthreads();
        fwd_stage1(s_img, s_T1, s_w, tid, bd);
        __syncthreads();
        const float2* Gt = d_G + (b*2 + ch)*SPEC;
        for (int c = tid; c < SS*26; c += bd){
            int k1 = c / 26, k2b = (c % 26) * 4;
            float2 w[4], st[4], acc[4];
#pragma unroll
            for (int j = 0; j < 4; j++){
                w[j] = make_float2(1.f, 0.f); st[j] = s_w[k2b + j]; acc[j] = make_float2(0.f, 0.f);
            }
            for (int x = 0; x < SIDE; x++){
                float2 tv = s_T1[k1*SIDE + x];
#pragma unroll
                for (int j = 0; j < 4; j++){
                    acc[j].x = fmaf(tv.x, w[j].x, fmaf(-tv.y, w[j].y, acc[j].x));
                    acc[j].y = fmaf(tv.x, w[j].y, fmaf( tv.y, w[j].x, acc[j].y));
                    w[j] = cmul(w[j], st[j]);
                }
            }
#pragma unroll
            for (int j = 0; j < 4; j++){
                int k2 = k2b + j;
                if (k2 < KH){
                    int o = k1*KH + k2;
                    float2 v = cmul(acc[j], Gt[o]);
                    float2* dst = &d_SF[img*SPEC + o];
                    if (ch == 0) *dst = v;
                    else { float2 pv = *dst; pv.x += v.x; pv.y += v.y; *dst = pv; }
                }
            }
        }
        __syncthreads();
    }
}

// ---------------- inverse stage 1 (over k1), fold Hermitian weight + 1/S^2 ----------------
__global__ void k_ifft1(){
    extern __shared__ float sm[];
    float2* s_S = (float2*)sm;
    float2* s_w = s_S + SPEC;
    int tid = threadIdx.x, bd = blockDim.x;
    int img = blockIdx.x;
    const float2* src = d_SF + img*SPEC;
    for (int i = tid; i < SPEC; i += bd) s_S[i] = src[i];
    for (int i = tid; i < SS;   i += bd) s_w[i] = d_wi[i];
    __syncthreads();
    for (int c = tid; c < 5050; c += bd){
        int k2 = c % KH, yb = (c / KH) * 4;
        float2 w[4], st[4], acc[4];
#pragma unroll
        for (int j = 0; j < 4; j++){
            w[j] = make_float2(1.f, 0.f); st[j] = s_w[yb + j]; acc[j] = make_float2(0.f, 0.f);
        }
        for (int k1 = 0; k1 < SS; k1++){
            float2 sv = s_S[k1*KH + k2];
#pragma unroll
            for (int j = 0; j < 4; j++){
                acc[j].x = fmaf(sv.x, w[j].x, fmaf(-sv.y, w[j].y, acc[j].x));
                acc[j].y = fmaf(sv.x, w[j].y, fmaf( sv.y, w[j].x, acc[j].y));
                w[j] = cmul(w[j], st[j]);
            }
        }
        float scale = (k2 == 0 || k2 == KH-1) ? (1.f/40000.f) : (2.f/40000.f);
#pragma unroll
        for (int j = 0; j < 4; j++)
            d_Binv[img*SPEC + (yb + j)*KH + k2] = make_float2(acc[j].x*scale, acc[j].y*scale);
    }
}

// ---------------- inverse stage 2 (real, over k2) + max-reduce + gather ----------------
__global__ void k_ifft2(const int* __restrict__ gt_rot, const int* __restrict__ gt_txy){
    extern __shared__ float sm[];
    float2* s_B = (float2*)sm;
    float2* s_w = s_B + SPEC;
    __shared__ float red[512];
    int tid = threadIdx.x, bd = blockDim.x;
    int img = blockIdx.x;
    int b = img / RR, r = img % RR;
    const float2* src = d_Binv + img*SPEC;
    for (int i = tid; i < SPEC; i += bd) s_B[i] = src[i];
    for (int i = tid; i < SS;   i += bd) s_w[i] = d_wi[i];
    __syncthreads();
    int gtr = gt_rot[b];
    int ty = gt_txy[2*b], tx = gt_txy[2*b + 1];
    float lm = -FLT_MAX;
    for (int c = tid; c < 10000; c += bd){
        int y = c / 50, xb = (c % 50) * 4;
        float2 w[4], st[4];
        float acc[4];
#pragma unroll
        for (int j = 0; j < 4; j++){
            w[j] = make_float2(1.f, 0.f); st[j] = s_w[xb + j]; acc[j] = 0.f;
        }
        for (int k2 = 0; k2 < KH; k2++){
            float2 bv = s_B[y*KH + k2];
#pragma unroll
            for (int j = 0; j < 4; j++){
                acc[j] = fmaf(bv.x, w[j].x, acc[j]);
                acc[j] = fmaf(-bv.y, w[j].y, acc[j]);
                w[j] = cmul(w[j], st[j]);
            }
        }
#pragma unroll
        for (int j = 0; j < 4; j++){
            lm = fmaxf(lm, acc[j]);
            if (r == gtr && y == ty && (xb + j) == tx) d_pos[b] = acc[j];
        }
    }
    red[tid] = lm;
    __syncthreads();
    for (int s = bd >> 1; s > 0; s >>= 1){
        if (tid < s) red[tid] = fmaxf(red[tid], red[tid + s]);
        __syncthreads();
    }
    if (tid == 0) d_blockmax[img] = red[0];
}

// ---------------- final reduction + loss ----------------
__global__ void k_final(float* __restrict__ out){
    __shared__ float r0[512], r1[512];
    int tid = threadIdx.x;
    float m0 = -FLT_MAX, m1 = -FLT_MAX;
    if (tid < RR){ m0 = d_blockmax[tid]; m1 = d_blockmax[RR + tid]; }
    r0[tid] = m0; r1[tid] = m1;
    __syncthreads();
    for (int s = 256; s > 0; s >>= 1){
        if (tid < s){ r0[tid] = fmaxf(r0[tid], r0[tid+s]); r1[tid] = fmaxf(r1[tid], r1[tid+s]); }
        __syncthreads();
    }
    if (tid == 0){
        float p0 = d_pos[0], p1 = d_pos[1];
        float b0 = r0[0], b1 = r1[0];
        float Lp = 0.5f * ((p0 + p0*p0) + (p1 + p1*p1));
        float Ln = 0.5f * ((-b0 + b0*b0) + (-b1 + b1*b1));
        out[0] = Lp;
        out[1] = Ln;
    }
}

// ---------------- launch ----------------
extern "C" void kernel_launch(void* const* d_in, const int* in_sizes, int n_in,
                              void* d_out, int out_size){
    const float* rec = (const float*)d_in[0];
    const float* lig = (const float*)d_in[1];
    const float* w1  = (const float*)d_in[2];
    const float* w2  = (const float*)d_in[3];
    const float* bW  = (const float*)d_in[4];
    const float* c1  = (const float*)d_in[5];
    const float* c2  = (const float*)d_in[6];
    const float* bu  = (const float*)d_in[7];
    const int*   gtr = (const int*)d_in[8];
    const int*   gtx = (const int*)d_in[9];
    float* out = (float*)d_out;

    const int FWD_SMEM = NPIX*4 + SS*SIDE*8 + SS*8;   // 201600
    const int INV_SMEM = SPEC*8 + SS*8;               // 163200
    cudaFuncSetAttribute(k_fft_rec, cudaFuncAttributeMaxDynamicSharedMemorySize, FWD_SMEM);
    cudaFuncSetAttribute(k_fft_lig, cudaFuncAttributeMaxDynamicSharedMemorySize, FWD_SMEM);
    cudaFuncSetAttribute(k_ifft1,   cudaFuncAttributeMaxDynamicSharedMemorySize, INV_SMEM);
    cudaFuncSetAttribute(k_ifft2,   cudaFuncAttributeMaxDynamicSharedMemorySize, INV_SMEM);

    k_init<<<1, 512>>>();
    k_conv1<<<(4*NPIX + 255)/256, 256>>>(rec, lig, w1);
    k_conv2<<<(4*NPIX + 255)/256, 256>>>(w2);
    k_rot<<<(NIMG*NPIX + 255)/256, 256>>>();
    k_fft_rec<<<4, 512, FWD_SMEM>>>();
    k_gcoef<<<(NB*SPEC + 255)/256, 256>>>(bW, c1, c2, bu);
    k_fft_lig<<<NIMG, 512, FWD_SMEM>>>();
    k_ifft1<<<NIMG, 512, INV_SMEM>>>();
    k_ifft2<<<NIMG, 512, INV_SMEM>>>(gtr, gtx);
    k_final<<<1, 512>>>(out);
}

// round 7
// speedup vs baseline: 1.1332x; 1.1332x over previous
#include <cuda_runtime.h>
#include <math.h>
#include <cfloat>

#ifndef M_PI
#define M_PI 3.14159265358979323846
#endif

typedef unsigned long long u64;

#define NPIX 10000      // 100*100
#define SIDE 100
#define SS   200
#define KH   101        // rfft half-width
#define RR   360
#define NB   2
#define NIMG (NB*RR)    // 720
#define SPEC (SS*KH)    // 20200
#define EPSF 1e-12f
#define T1PITCH 201
#define SPITCH  105

// ---------------- static device scratch ----------------
__device__ float  d_h1[4*9*NPIX];
__device__ float  d_feat[4*2*NPIX];
__device__ float  d_rot[NIMG*2*NPIX];
__device__ float2 d_rf[4*SPEC];            // [q][k2*200 + k1]
__device__ float2 d_G[4*SPEC];             // [q][k2*200 + k1]
__device__ float2 d_SF[NIMG*SPEC];         // [img][k2*200 + k1]
__device__ float2 d_Binv[NIMG*SPEC];       // [img][k2*200 + y]
__device__ float  d_blockmax[NIMG];
__device__ float  d_pos[NB];
__device__ float2 d_rtrig[RR];
__device__ u64        d_tw1f[SS];          // (c, -s)         fwd stage1
__device__ u64        d_tw1i[SS];          // (c,  s)         ifft2
__device__ ulonglong2 d_tw2f[SS];          // ((c,-s),(-s,c)) fwd stage2
__device__ ulonglong2 d_tw2i[SS];          // ((c, s),( s,c)) ifft1

// ---------------- packed f32x2 helpers ----------------
__device__ __forceinline__ u64 pk2(float a, float b){
    u64 r; asm("mov.b64 %0, {%1, %2};" : "=l"(r) : "f"(a), "f"(b)); return r;
}
__device__ __forceinline__ float2 up2(u64 v){
    float2 r; asm("mov.b64 {%0, %1}, %2;" : "=f"(r.x), "=f"(r.y) : "l"(v)); return r;
}
__device__ __forceinline__ u64 ffma2(u64 a, u64 b, u64 c){
    u64 d; asm("fma.rn.f32x2 %0, %1, %2, %3;" : "=l"(d) : "l"(a), "l"(b), "l"(c)); return d;
}

// ---------------- init tables ----------------
__global__ void k_init(){
    int t = threadIdx.x;
    if (t < SS){
        double th = 2.0 * M_PI * (double)t / 200.0;
        float c = (float)cos(th), s = (float)sin(th);
        d_tw1f[t] = pk2(c, -s);
        d_tw1i[t] = pk2(c,  s);
        d_tw2f[t] = make_ulonglong2(pk2(c, -s), pk2(-s, c));
        d_tw2i[t] = make_ulonglong2(pk2(c,  s), pk2( s, c));
    }
    if (t < RR){
        double th = -M_PI + (double)t * (2.0 * M_PI / 360.0);
        d_rtrig[t] = make_float2((float)cos(th), (float)sin(th));
    }
}

// ---------------- conv1 + field norm ----------------
__global__ void k_conv1(const float* __restrict__ rec, const float* __restrict__ lig,
                        const float* __restrict__ w1){
    int idx = blockIdx.x*blockDim.x + threadIdx.x;
    if (idx >= 4*NPIX) return;
    int t = idx / NPIX, p = idx % NPIX;
    int y = p / SIDE, x = p % SIDE;
    const float* src = (t < 2) ? rec + t*NPIX : lig + (t-2)*NPIX;
    float acc[9];
#pragma unroll
    for (int o = 0; o < 9; o++) acc[o] = 0.f;
    for (int dy = 0; dy < 5; dy++){
        int yy = y + dy - 2; if (yy < 0 || yy >= SIDE) continue;
        for (int dx = 0; dx < 5; dx++){
            int xx = x + dx - 2; if (xx < 0 || xx >= SIDE) continue;
            float v = src[yy*SIDE + xx];
#pragma unroll
            for (int o = 0; o < 9; o++) acc[o] = fmaf(w1[o*25 + dy*5 + dx], v, acc[o]);
        }
    }
    float out[9];
    { float n = sqrtf(acc[0]*acc[0] + EPSF); out[0] = acc[0] * (n/(n+EPSF)); }
#pragma unroll
    for (int g = 0; g < 4; g++){
        int a = 1 + 2*g;
        float n = sqrtf(acc[a]*acc[a] + acc[a+1]*acc[a+1] + EPSF);
        float s = n/(n+EPSF);
        out[a] = acc[a]*s; out[a+1] = acc[a+1]*s;
    }
#pragma unroll
    for (int o = 0; o < 9; o++) d_h1[(t*9 + o)*NPIX + p] = out[o];
}

// ---------------- conv2 + field norm + features ----------------
__global__ void k_conv2(const float* __restrict__ w2){
    int idx = blockIdx.x*blockDim.x + threadIdx.x;
    if (idx >= 4*NPIX) return;
    int t = idx / NPIX, p = idx % NPIX;
    int y = p / SIDE, x = p % SIDE;
    float h[3] = {0.f, 0.f, 0.f};
    for (int ic = 0; ic < 9; ic++){
        const float* base = d_h1 + (t*9 + ic)*NPIX;
        for (int dy = 0; dy < 5; dy++){
            int yy = y + dy - 2; if (yy < 0 || yy >= SIDE) continue;
            for (int dx = 0; dx < 5; dx++){
                int xx = x + dx - 2; if (xx < 0 || xx >= SIDE) continue;
                float v = base[yy*SIDE + xx];
#pragma unroll
                for (int oc = 0; oc < 3; oc++)
                    h[oc] = fmaf(w2[(oc*9 + ic)*25 + dy*5 + dx], v, h[oc]);
            }
        }
    }
    float n0 = sqrtf(h[0]*h[0] + EPSF);
    float o0 = h[0] * (n0/(n0+EPSF));
    float n1 = sqrtf(h[1]*h[1] + h[2]*h[2] + EPSF);
    float s  = n1/(n1+EPSF);
    float o1 = h[1]*s, o2 = h[2]*s;
    d_feat[(t*2 + 0)*NPIX + p] = fabsf(o0);
    d_feat[(t*2 + 1)*NPIX + p] = sqrtf(o1*o1 + o2*o2 + EPSF);
}

// ---------------- bilinear rotation ----------------
__global__ void k_rot(){
    int idx = blockIdx.x*blockDim.x + threadIdx.x;
    if (idx >= NIMG*NPIX) return;
    int img = idx / NPIX, p = idx % NPIX;
    int b = img / RR, r = img % RR;
    int i = p / SIDE, j = p % SIDE;
    float2 cs = d_rtrig[r];
    float ct = cs.x, st = cs.y;
    const float c = 49.5f;
    float xs = (float)j - c, ys = (float)i - c;
    float xq =  ct*xs + st*ys + c;
    float yq = -st*xs + ct*ys + c;
    float x0f = floorf(xq), y0f = floorf(yq);
    float wx = xq - x0f, wy = yq - y0f;
    int x0 = (int)x0f, y0 = (int)y0f;
    float w00 = (1.f-wy)*(1.f-wx), w01 = (1.f-wy)*wx;
    float w10 = wy*(1.f-wx),       w11 = wy*wx;
    bool vx0 = (x0 >= 0 && x0 < SIDE), vx1 = (x0+1 >= 0 && x0+1 < SIDE);
    bool vy0 = (y0 >= 0 && y0 < SIDE), vy1 = (y0+1 >= 0 && y0+1 < SIDE);
    int cx0 = min(max(x0, 0), SIDE-1),   cx1 = min(max(x0+1, 0), SIDE-1);
    int cy0 = min(max(y0, 0), SIDE-1),   cy1 = min(max(y0+1, 0), SIDE-1);
#pragma unroll
    for (int ch = 0; ch < 2; ch++){
        const float* base = d_feat + ((2 + b)*2 + ch)*NPIX;
        float g00 = (vy0 && vx0) ? base[cy0*SIDE + cx0] : 0.f;
        float g01 = (vy0 && vx1) ? base[cy0*SIDE + cx1] : 0.f;
        float g10 = (vy1 && vx0) ? base[cy1*SIDE + cx0] : 0.f;
        float g11 = (vy1 && vx1) ? base[cy1*SIDE + cx1] : 0.f;
        d_rot[(img*2 + ch)*NPIX + p] = g00*w00 + g01*w01 + g10*w10 + g11*w11;
    }
}

// ---------------- forward rfft2 (packed FFMA2, twiddle-table broadcast) ----------------
// lig_mode=0: grid 2 blocks (b); writes d_rf[q = b*2+ch]
// lig_mode=1: grid 720 blocks (img); writes/accumulates d_SF via d_G
__global__ void __launch_bounds__(512, 1) k_fwd(int lig_mode){
    extern __shared__ char sm[];
    ulonglong2* s_tw2 = (ulonglong2*)sm;              // 3200 B
    u64*        s_tw1 = (u64*)(sm + 3200);            // 1600 B
    float*      s_img = (float*)(sm + 4800);          // 40000 B
    float2*     s_T1  = (float2*)(sm + 44800);        // 100*201*8 = 160800 B
    int tid = threadIdx.x, lane = tid & 31, warp = tid >> 5;
    int img = blockIdx.x;
    int b = lig_mode ? (img / RR) : img;

    for (int i = tid; i < SS; i += 512){ s_tw1[i] = d_tw1f[i]; s_tw2[i] = d_tw2f[i]; }

    for (int ch = 0; ch < 2; ch++){
        const float* src = lig_mode ? (d_rot + (img*2 + ch)*NPIX)
                                    : (d_feat + (img*2 + ch)*NPIX);
        for (int i = tid; i < NPIX; i += 512) s_img[i] = src[i];
        __syncthreads();

        // stage 1: T1[k1][x] = sum_y img[y][x] * e^{-2pi i k1 y /200}; stored [x][k1]
        for (int tile = warp; tile < 50; tile += 16){
            int k1b = tile * 4;
            u64 acc[4][4];
#pragma unroll
            for (int j = 0; j < 4; j++)
#pragma unroll
                for (int m = 0; m < 4; m++) acc[j][m] = 0ull;
            int idx[4] = {0, 0, 0, 0};
            for (int y = 0; y < 100; y++){
                const float* row = s_img + y*SIDE;
                float v0 = row[lane], v1 = row[lane+32], v2 = row[lane+64];
                float v3 = (lane < 4) ? row[lane+96] : 0.f;
                u64 V[4] = {pk2(v0,v0), pk2(v1,v1), pk2(v2,v2), pk2(v3,v3)};
#pragma unroll
                for (int j = 0; j < 4; j++){
                    u64 w = s_tw1[idx[j]];
#pragma unroll
                    for (int m = 0; m < 4; m++) acc[j][m] = ffma2(V[m], w, acc[j][m]);
                    idx[j] += k1b + j; if (idx[j] >= 200) idx[j] -= 200;
                }
            }
#pragma unroll
            for (int j = 0; j < 4; j++)
#pragma unroll
                for (int m = 0; m < 4; m++){
                    if (m < 3 || lane < 4){
                        int x = lane + 32*m;
                        s_T1[x*T1PITCH + k1b + j] = up2(acc[j][m]);
                    }
                }
        }
        __syncthreads();

        // stage 2: C[k1][k2] = sum_x T1[k1][x] * e^{-2pi i k2 x /200}
        float2* gout = lig_mode ? (d_SF + img*SPEC) : (d_rf + (img*2 + ch)*SPEC);
        const float2* gG = lig_mode ? (d_G + (b*2 + ch)*SPEC) : (const float2*)0;
        for (int u = warp; u < 104; u += 16){
            int k2t = u >> 2, pass = u & 3;
            int k2b = k2t * 4;
            int k1m0 = pass*64 + lane, k1m1 = k1m0 + 32;
            bool va0 = k1m0 < 200, va1 = k1m1 < 200;
            int k1c0 = min(k1m0, 199), k1c1 = min(k1m1, 199);
            u64 P1[4][2], P2[4][2];
#pragma unroll
            for (int j = 0; j < 4; j++){ P1[j][0]=0ull; P1[j][1]=0ull; P2[j][0]=0ull; P2[j][1]=0ull; }
            int idx[4] = {0, 0, 0, 0};
            for (int x = 0; x < 100; x++){
                float2 t0 = s_T1[x*T1PITCH + k1c0];
                float2 t1 = s_T1[x*T1PITCH + k1c1];
                u64 Tx0 = pk2(t0.x, t0.x), Ty0 = pk2(t0.y, t0.y);
                u64 Tx1 = pk2(t1.x, t1.x), Ty1 = pk2(t1.y, t1.y);
#pragma unroll
                for (int j = 0; j < 4; j++){
                    ulonglong2 wv = s_tw2[idx[j]];
                    P1[j][0] = ffma2(Tx0, wv.x, P1[j][0]);
                    P2[j][0] = ffma2(Ty0, wv.y, P2[j][0]);
                    P1[j][1] = ffma2(Tx1, wv.x, P1[j][1]);
                    P2[j][1] = ffma2(Ty1, wv.y, P2[j][1]);
                    idx[j] += k2b + j; if (idx[j] >= 200) idx[j] -= 200;
                }
            }
#pragma unroll
            for (int j = 0; j < 4; j++){
                int k2 = k2b + j;
                if (k2 >= KH) continue;
#pragma unroll
                for (int m = 0; m < 2; m++){
                    bool va = (m == 0) ? va0 : va1;
                    if (!va) continue;
                    int k1 = (m == 0) ? k1m0 : k1m1;
                    float2 p1 = up2(P1[j][m]), p2 = up2(P2[j][m]);
                    float2 C = make_float2(p1.x - p2.x, p1.y + p2.y);
                    int o = k2*200 + k1;
                    if (lig_mode){
                        float2 g = gG[o];
                        float2 v = make_float2(C.x*g.x - C.y*g.y, C.x*g.y + C.y*g.x);
                        if (ch == 0) gout[o] = v;
                        else { float2 pv = gout[o]; gout[o] = make_float2(pv.x + v.x, pv.y + v.y); }
                    } else {
                        gout[o] = C;
                    }
                }
            }
        }
        __threadfence_block();
        __syncthreads();
    }
}

// ---------------- combine coefficients ----------------
__global__ void k_gcoef(const float* __restrict__ bW, const float* __restrict__ c1,
                        const float* __restrict__ c2, const float* __restrict__ bu){
    int idx = blockIdx.x*blockDim.x + threadIdx.x;
    if (idx >= NB*SPEC) return;
    int b = idx / SPEC, i = idx % SPEC;
    float2 rb = d_rf[(b*2 + 0)*SPEC + i];
    float2 rB = d_rf[(b*2 + 1)*SPEC + i];
    float2 crb = make_float2(rb.x, -rb.y);
    float2 crB = make_float2(rB.x, -rB.y);
    float wb = bW[0], wc1 = c1[0], wc2 = c2[0], wk = bu[0];
    d_G[(b*2 + 0)*SPEC + i] = make_float2(wb*crb.x + wc2*crB.x,  wb*crb.y + wc2*crB.y);
    d_G[(b*2 + 1)*SPEC + i] = make_float2(wc1*crb.x - wk*crB.x,  wc1*crb.y - wk*crB.y);
}

// ---------------- inverse stage 1 over k1 (packed) ----------------
// Binv[k2][y] = scale(k2) * sum_k1 SF[k2][k1] * e^{+2pi i k1 y /200}
__global__ void __launch_bounds__(512, 1) k_ifft1(){
    extern __shared__ char sm[];
    ulonglong2* s_tw2 = (ulonglong2*)sm;            // 3200 B
    float2*     s_S   = (float2*)(sm + 3200);       // 200*105*8 = 168000 B, [k1][k2]
    int tid = threadIdx.x, lane = tid & 31, warp = tid >> 5;
    int img = blockIdx.x;
    const float2* src = d_SF + img*SPEC;
    for (int i = tid; i < SS; i += 512) s_tw2[i] = d_tw2i[i];
    for (int i = tid; i < SPEC; i += 512){
        int k2 = i / 200, k1 = i - k2*200;
        s_S[k1*SPITCH + k2] = src[i];
    }
    __syncthreads();

    for (int u = warp; u < 100; u += 16){
        int yt = u >> 1, pass = u & 1;
        int k2m0 = pass*64 + lane, k2m1 = k2m0 + 32;
        bool va0 = k2m0 <= 100, va1 = k2m1 <= 100;
        int k2c0 = min(k2m0, 100), k2c1 = min(k2m1, 100);
        u64 P1[4][2], P2[4][2];
#pragma unroll
        for (int j = 0; j < 4; j++){ P1[j][0]=0ull; P1[j][1]=0ull; P2[j][0]=0ull; P2[j][1]=0ull; }
        int idx[4] = {0, 0, 0, 0};
        for (int k1 = 0; k1 < 200; k1++){
            float2 t0 = s_S[k1*SPITCH + k2c0];
            float2 t1 = s_S[k1*SPITCH + k2c1];
            u64 Tx0 = pk2(t0.x, t0.x), Ty0 = pk2(t0.y, t0.y);
            u64 Tx1 = pk2(t1.x, t1.x), Ty1 = pk2(t1.y, t1.y);
#pragma unroll
            for (int j = 0; j < 4; j++){
                ulonglong2 wv = s_tw2[idx[j]];
                P1[j][0] = ffma2(Tx0, wv.x, P1[j][0]);
                P2[j][0] = ffma2(Ty0, wv.y, P2[j][0]);
                P1[j][1] = ffma2(Tx1, wv.x, P1[j][1]);
                P2[j][1] = ffma2(Ty1, wv.y, P2[j][1]);
                idx[j] += yt*4 + j; if (idx[j] >= 200) idx[j] -= 200;
            }
        }
#pragma unroll
        for (int j = 0; j < 4; j++){
            int y = yt*4 + j;
#pragma unroll
            for (int m = 0; m < 2; m++){
                bool va = (m == 0) ? va0 : va1;
                if (!va) continue;
                int k2 = (m == 0) ? k2m0 : k2m1;
                float2 p1 = up2(P1[j][m]), p2 = up2(P2[j][m]);
                float sc = (k2 == 0 || k2 == 100) ? 2.5e-5f : 5.0e-5f;
                d_Binv[img*SPEC + k2*200 + y] = make_float2((p1.x - p2.x)*sc, (p1.y + p2.y)*sc);
            }
        }
    }
}

// ---------------- inverse stage 2 over k2 (real, packed-term trick) + max + gather ----------------
// s[y][x] = sum_{k2} (B.x*c - B.y*s), (c,s)=e^{+2pi i k2 x /200}
__global__ void __launch_bounds__(512, 1) k_ifft2(const int* __restrict__ gt_rot,
                                                  const int* __restrict__ gt_txy){
    extern __shared__ char sm[];
    u64* s_tw = (u64*)sm;                 // 1600 B
    u64* s_B  = (u64*)(sm + 1600);        // SPEC*8 = 161600 B, [k2][y] as packed float2
    __shared__ float red[512];
    int tid = threadIdx.x, lane = tid & 31, warp = tid >> 5;
    int img = blockIdx.x;
    int b = img / RR, r = img % RR;
    const u64* src = (const u64*)(d_Binv + img*SPEC);
    for (int i = tid; i < SS; i += 512) s_tw[i] = d_tw1i[i];
    for (int i = tid; i < SPEC; i += 512) s_B[i] = src[i];
    __syncthreads();

    int gtr = gt_rot[b];
    int ty = gt_txy[2*b], tx = gt_txy[2*b + 1];
    float lm = -FLT_MAX;

    for (int u = warp; u < 50; u += 16){
        int xt = u >> 1, pass = u & 1;
        int xb = xt * 8;
        int ym[4]; bool vy[4]; int yc[4];
#pragma unroll
        for (int m = 0; m < 4; m++){
            ym[m] = pass*128 + lane + 32*m;
            vy[m] = ym[m] < 200;
            yc[m] = min(ym[m], 199);
        }
        u64 acc[8][4];
#pragma unroll
        for (int i = 0; i < 8; i++)
#pragma unroll
            for (int m = 0; m < 4; m++) acc[i][m] = 0ull;
        int idx[8] = {0,0,0,0,0,0,0,0};
        for (int k2 = 0; k2 <= 100; k2++){
            u64 B0 = s_B[k2*200 + yc[0]];
            u64 B1 = s_B[k2*200 + yc[1]];
            u64 B2 = s_B[k2*200 + yc[2]];
            u64 B3 = s_B[k2*200 + yc[3]];
#pragma unroll
            for (int i = 0; i < 8; i++){
                u64 w = s_tw[idx[i]];
                acc[i][0] = ffma2(B0, w, acc[i][0]);
                acc[i][1] = ffma2(B1, w, acc[i][1]);
                acc[i][2] = ffma2(B2, w, acc[i][2]);
                acc[i][3] = ffma2(B3, w, acc[i][3]);
                idx[i] += xb + i; if (idx[i] >= 200) idx[i] -= 200;
            }
        }
#pragma unroll
        for (int i = 0; i < 8; i++){
            int x = xb + i;
#pragma unroll
            for (int m = 0; m < 4; m++){
                if (!vy[m]) continue;
                float2 a = up2(acc[i][m]);
                float v = a.x - a.y;
                lm = fmaxf(lm, v);
                if (r == gtr && ym[m] == ty && x == tx) d_pos[b] = v;
            }
        }
    }
    red[tid] = lm;
    __syncthreads();
    for (int s = 256; s > 0; s >>= 1){
        if (tid < s) red[tid] = fmaxf(red[tid], red[tid + s]);
        __syncthreads();
    }
    if (tid == 0) d_blockmax[img] = red[0];
}

// ---------------- final reduction + loss ----------------
__global__ void k_final(float* __restrict__ out){
    __shared__ float r0[512], r1[512];
    int tid = threadIdx.x;
    float m0 = -FLT_MAX, m1 = -FLT_MAX;
    if (tid < RR){ m0 = d_blockmax[tid]; m1 = d_blockmax[RR + tid]; }
    r0[tid] = m0; r1[tid] = m1;
    __syncthreads();
    for (int s = 256; s > 0; s >>= 1){
        if (tid < s){ r0[tid] = fmaxf(r0[tid], r0[tid+s]); r1[tid] = fmaxf(r1[tid], r1[tid+s]); }
        __syncthreads();
    }
    if (tid == 0){
        float p0 = d_pos[0], p1 = d_pos[1];
        float b0 = r0[0], b1 = r1[0];
        out[0] = 0.5f * ((p0 + p0*p0) + (p1 + p1*p1));
        out[1] = 0.5f * ((-b0 + b0*b0) + (-b1 + b1*b1));
    }
}

// ---------------- launch ----------------
extern "C" void kernel_launch(void* const* d_in, const int* in_sizes, int n_in,
                              void* d_out, int out_size){
    const float* rec = (const float*)d_in[0];
    const float* lig = (const float*)d_in[1];
    const float* w1  = (const float*)d_in[2];
    const float* w2  = (const float*)d_in[3];
    const float* bW  = (const float*)d_in[4];
    const float* c1  = (const float*)d_in[5];
    const float* c2  = (const float*)d_in[6];
    const float* bu  = (const float*)d_in[7];
    const int*   gtr = (const int*)d_in[8];
    const int*   gtx = (const int*)d_in[9];
    float* out = (float*)d_out;

    const int FWD_SMEM  = 3200 + 1600 + NPIX*4 + SIDE*T1PITCH*8;   // 205600
    const int I1_SMEM   = 3200 + SS*SPITCH*8;                      // 171200
    const int I2_SMEM   = 1600 + SPEC*8;                           // 163200
    cudaFuncSetAttribute(k_fwd,   cudaFuncAttributeMaxDynamicSharedMemorySize, FWD_SMEM);
    cudaFuncSetAttribute(k_ifft1, cudaFuncAttributeMaxDynamicSharedMemorySize, I1_SMEM);
    cudaFuncSetAttribute(k_ifft2, cudaFuncAttributeMaxDynamicSharedMemorySize, I2_SMEM);

    k_init<<<1, 512>>>();
    k_conv1<<<(4*NPIX + 255)/256, 256>>>(rec, lig, w1);
    k_conv2<<<(4*NPIX + 255)/256, 256>>>(w2);
    k_rot<<<(NIMG*NPIX + 255)/256, 256>>>();
    k_fwd<<<NB, 512, FWD_SMEM>>>(0);
    k_gcoef<<<(NB*SPEC + 255)/256, 256>>>(bW, c1, c2, bu);
    k_fwd<<<NIMG, 512, FWD_SMEM>>>(1);
    k_ifft1<<<NIMG, 512, I1_SMEM>>>();
    k_ifft2<<<NIMG, 512, I2_SMEM>>>(gtr, gtx);
    k_final<<<1, 512>>>(out);
}